// round 1
// baseline (speedup 1.0000x reference)
#include <cuda_runtime.h>
#include <math.h>

#define BB 8
#define NN 2048
#define FF 64
#define TI 64
#define TJ 64
#define PT_STRIDE 68   // pT row stride (floats), keeps 16B alignment for float4 reads

// Scratch (allocation-free rule: device globals)
__device__ __align__(16) float g_h[BB * NN * FF];
__device__ __align__(16) float g_f1[BB * NN];
__device__ __align__(16) float g_f2[BB * NN];

// ---------------------------------------------------------------------------
// Kernel 1: h = inp @ W   (rows of inp are independent of batch structure)
// block: 256 threads, 16 rows per block. grid = 16384/16 = 1024
// ---------------------------------------------------------------------------
__global__ void __launch_bounds__(256) k_h(const float* __restrict__ inp,
                                           const float* __restrict__ W) {
    __shared__ float Ws[FF * FF];     // [k][c]
    __shared__ float Is[16 * FF];     // [r][k]
    const int t = threadIdx.x;
    const int row0 = blockIdx.x * 16;

    {
        float4* d = (float4*)Ws;
        const float4* s = (const float4*)W;
#pragma unroll
        for (int u = 0; u < 4; ++u) d[t + 256 * u] = s[t + 256 * u];
        ((float4*)Is)[t] = ((const float4*)(inp + (size_t)row0 * FF))[t];
    }
    __syncthreads();

    const int c = t & 63;
    const int rq = t >> 6;           // 0..3, owns rows rq*4 .. rq*4+3
    float acc[4] = {0.f, 0.f, 0.f, 0.f};
#pragma unroll 16
    for (int k = 0; k < FF; ++k) {
        float w = Ws[k * FF + c];
#pragma unroll
        for (int rr = 0; rr < 4; ++rr)
            acc[rr] += Is[(rq * 4 + rr) * FF + k] * w;
    }
#pragma unroll
    for (int rr = 0; rr < 4; ++rr)
        g_h[(size_t)(row0 + rq * 4 + rr) * FF + c] = acc[rr];
}

// ---------------------------------------------------------------------------
// Kernel 2: f1 = h@a1, f2 = h@a2. One warp per row. grid = 16384/8 = 2048
// ---------------------------------------------------------------------------
__global__ void __launch_bounds__(256) k_f(const float* __restrict__ a) {
    const int w = threadIdx.x >> 5;
    const int lane = threadIdx.x & 31;
    const int r = blockIdx.x * 8 + w;
    const float h0 = g_h[(size_t)r * FF + lane];
    const float h1 = g_h[(size_t)r * FF + 32 + lane];
    float s1 = h0 * a[lane]      + h1 * a[lane + 32];
    float s2 = h0 * a[64 + lane] + h1 * a[96 + lane];
#pragma unroll
    for (int o = 16; o > 0; o >>= 1) {
        s1 += __shfl_xor_sync(0xffffffffu, s1, o);
        s2 += __shfl_xor_sync(0xffffffffu, s2, o);
    }
    if (lane == 0) { g_f1[r] = s1; g_f2[r] = s2; }
}

// ---------------------------------------------------------------------------
// Kernel 3: fused masked-softmax attention + P@h + ELU (flash-style, online
// softmax; P never touches global memory).
// grid = (N/TI=32, B=8) = 256 CTAs, 256 threads.
// Each CTA: 64 rows of one batch, loops 32 j-tiles of 64.
// ---------------------------------------------------------------------------
__global__ void __launch_bounds__(256) k_attn(const int* __restrict__ adj,
                                              float* __restrict__ out) {
    __shared__ float h_s[TJ * FF];          // [j][c]  16 KB
    __shared__ float pT[TJ * PT_STRIDE];    // [j][r]  17 KB (transposed p)
    __shared__ float f2s[TJ];
    __shared__ float f1s[TI];
    __shared__ float Mrow[TI];
    __shared__ float Srow[TI];
    __shared__ float Frow[TI];

    const int b  = blockIdx.y;
    const int i0 = blockIdx.x * TI;
    const int t  = threadIdx.x;

    // score-phase mapping: 4 threads per row, 16 j's each
    const int sr = t >> 2;      // row 0..63
    const int sg = t & 3;       // j-group 0..3
    // gemm-phase mapping: 16x16 threads, 4x4 tile each
    const int tx = t & 15;
    const int ty = t >> 4;

    if (t < TI) {
        f1s[t]  = g_f1[b * NN + i0 + t];
        Mrow[t] = -1e30f;
        Srow[t] = 0.f;
    }
    float acc[4][4];
#pragma unroll
    for (int i = 0; i < 4; ++i)
#pragma unroll
        for (int j = 0; j < 4; ++j) acc[i][j] = 0.f;

    const float* hb = g_h + (size_t)b * NN * FF;
    const int* arow = adj + ((size_t)b * NN + i0 + sr) * NN;

    __syncthreads();

    for (int j0 = 0; j0 < NN; j0 += TJ) {
        // ---- load h tile + f2 tile ----
        {
            const float4* s = (const float4*)(hb + (size_t)j0 * FF);
            float4* d = (float4*)h_s;
#pragma unroll
            for (int u = 0; u < 4; ++u) d[t + 256 * u] = s[t + 256 * u];
            if (t < TJ / 4)
                ((float4*)f2s)[t] = ((const float4*)(g_f2 + b * NN + j0))[t];
        }
        __syncthreads();

        // ---- masked scores + online softmax update, stage p^T to smem ----
        {
            const float f1v = f1s[sr];
            float f2l[16];
#pragma unroll
            for (int u = 0; u < 4; ++u)
                ((float4*)f2l)[u] = ((const float4*)f2s)[sg * 4 + u];

            int4 av[4];
            const int4* ap = (const int4*)(arow + j0 + sg * 16);
#pragma unroll
            for (int u = 0; u < 4; ++u) av[u] = ap[u];
            const int* avi = (const int*)av;

            float e[16];
#pragma unroll
            for (int u = 0; u < 16; ++u) {
                float x = f1v + f2l[u];
                x = x > 0.f ? x : 0.2f * x;          // leaky relu, slope 0.2
                e[u] = avi[u] > 0 ? x : -9.0e15f;    // mask
            }
            float mx = e[0];
#pragma unroll
            for (int u = 1; u < 16; ++u) mx = fmaxf(mx, e[u]);
            mx = fmaxf(mx, __shfl_xor_sync(0xffffffffu, mx, 1));
            mx = fmaxf(mx, __shfl_xor_sync(0xffffffffu, mx, 2));

            const float Mold = Mrow[sr];
            const float Mnew = fmaxf(Mold, mx);
            float s = 0.f;
#pragma unroll
            for (int u = 0; u < 16; ++u) {
                float p = __expf(e[u] - Mnew);
                pT[(sg * 16 + u) * PT_STRIDE + sr] = p;
                s += p;
            }
            s += __shfl_xor_sync(0xffffffffu, s, 1);
            s += __shfl_xor_sync(0xffffffffu, s, 2);

            const float f = __expf(Mold - Mnew);
            // The 4 group-threads of a row live in one warp and write
            // identical values; reads above precede writes in issue order.
            Mrow[sr] = Mnew;
            Srow[sr] = Srow[sr] * f + s;
            Frow[sr] = f;
        }
        __syncthreads();

        // ---- rescale accumulators + 64x64x64 GEMM accumulate ----
        {
            float fr[4];
#pragma unroll
            for (int rr = 0; rr < 4; ++rr) fr[rr] = Frow[ty * 4 + rr];
#pragma unroll
            for (int rr = 0; rr < 4; ++rr)
#pragma unroll
                for (int cc = 0; cc < 4; ++cc) acc[rr][cc] *= fr[rr];

#pragma unroll 8
            for (int k = 0; k < TJ; ++k) {
                const float4 hv = *(const float4*)&h_s[k * FF + tx * 4];
                const float4 pv = *(const float4*)&pT[k * PT_STRIDE + ty * 4];
                const float ha[4] = {hv.x, hv.y, hv.z, hv.w};
                const float pa[4] = {pv.x, pv.y, pv.z, pv.w};
#pragma unroll
                for (int rr = 0; rr < 4; ++rr)
#pragma unroll
                    for (int cc = 0; cc < 4; ++cc)
                        acc[rr][cc] += pa[rr] * ha[cc];
            }
        }
        __syncthreads();
    }

    // ---- epilogue: divide by softmax denom, ELU, store ----
#pragma unroll
    for (int rr = 0; rr < 4; ++rr) {
        const int r = ty * 4 + rr;
        const float sv = 1.0f / Srow[r];
        float4 o;
        float v;
        v = acc[rr][0] * sv; o.x = v > 0.f ? v : expm1f(v);
        v = acc[rr][1] * sv; o.y = v > 0.f ? v : expm1f(v);
        v = acc[rr][2] * sv; o.z = v > 0.f ? v : expm1f(v);
        v = acc[rr][3] * sv; o.w = v > 0.f ? v : expm1f(v);
        *(float4*)(out + ((size_t)b * NN + i0 + r) * FF + tx * 4) = o;
    }
}

// ---------------------------------------------------------------------------
extern "C" void kernel_launch(void* const* d_in, const int* in_sizes, int n_in,
                              void* d_out, int out_size) {
    const float* inp = (const float*)d_in[0];
    const int*   adj = (const int*)d_in[1];
    const float* W   = (const float*)d_in[2];
    const float* a   = (const float*)d_in[3];
    float* out = (float*)d_out;

    k_h<<<(BB * NN) / 16, 256>>>(inp, W);
    k_f<<<(BB * NN) / 8, 256>>>(a);
    dim3 g(NN / TI, BB);
    k_attn<<<g, 256>>>(adj, out);
}